// round 6
// baseline (speedup 1.0000x reference)
#include <cuda_runtime.h>
#include <math.h>
#include <stdint.h>

#define B 64
#define T 128
#define M 4
#define D 512
#define H 512
#define LNUM 2
#define K 6
#define F5H 2560   // 5*H

#define AST 36     // k_share A smem row stride
#define BST 136    // k_share B smem row stride
#define SMEM_S ((2*64*AST*2 + 2*32*BST*2) * 4)

// k_gemm: Af 512 float4 + Bf 2080 float4
#define SMEM_G ((512 + 2080) * 16)

// ---------------- persistent scratch ----------------------------------------
__device__ float g_bufA[(size_t)T * B * 2 * D];
__device__ float g_bufB[(size_t)T * B * 2 * D];
__device__ float g_shareA[(size_t)T * B * H];
__device__ float g_shareB[(size_t)T * B * H];
__device__ float2 g_A[(size_t)128 * 4096];        // rows r=j*64+b, (hi,lo) split
__device__ float g_partial[(size_t)8 * 128 * F5H];
__device__ float g_cell[(size_t)B * 2 * H];
__device__ float g_shst[(size_t)B * H];
__device__ float g_cum[(size_t)B * H];
__device__ int   g_sel[B * 2 * 2];

__device__ __forceinline__ float to_tf32(float x) {
    float r; asm("cvt.rna.tf32.f32 %0, %1;" : "=f"(r) : "f"(x)); return r;
}
__device__ __forceinline__ void split2(float x, float& hi, float& lo) {
    hi = to_tf32(x);
    lo = to_tf32(x - hi);
}

__device__ __forceinline__ void mma8(float& c0, float& c1, float& c2, float& c3,
                                     uint32_t a0, uint32_t a1, uint32_t a2, uint32_t a3,
                                     uint32_t b0, uint32_t b1) {
    asm volatile("mma.sync.aligned.m16n8k8.row.col.f32.tf32.tf32.f32 "
                 "{%0,%1,%2,%3}, {%4,%5,%6,%7}, {%8,%9}, {%0,%1,%2,%3};"
                 : "+f"(c0), "+f"(c1), "+f"(c2), "+f"(c3)
                 : "r"(a0), "r"(a1), "r"(a2), "r"(a3), "r"(b0), "r"(b1));
}

// ---------------- 3xtf32 share GEMM: [8192,2048]@[2048,512]+bias+relu --------
__global__ __launch_bounds__(256) void k_share(const float* __restrict__ feat,
                                               const float* __restrict__ W,
                                               const float* __restrict__ bias) {
    int col0 = blockIdx.x * 128;
    int row0 = blockIdx.y * 64;
    const float* Abase = feat + (size_t)row0 * 2048;

    extern __shared__ float sm[];
    float* Ah = sm;
    float* Al = Ah + 2 * 64 * AST;
    float* Bh = Al + 2 * 64 * AST;
    float* Bl = Bh + 2 * 32 * BST;

    int tid = threadIdx.x;
    int warp = tid >> 5, lane = tid & 31;
    int wm = warp >> 2, wn = warp & 3;
    int tg = lane >> 2, tig = lane & 3;
    int ar = tid >> 3, ac = (tid & 7) * 4;
    int br = warp, bc = lane * 4;

    float acc[2][4][4];
#pragma unroll
    for (int a = 0; a < 2; a++)
#pragma unroll
        for (int b = 0; b < 4; b++)
#pragma unroll
            for (int c = 0; c < 4; c++) acc[a][b][c] = 0.f;

    {
        float4 v0 = *(const float4*)&Abase[(size_t)ar * 2048 + ac];
        float4 v1 = *(const float4*)&Abase[(size_t)(ar + 32) * 2048 + ac];
        float h0, l0;
        float* pa = (float*)&v0;
#pragma unroll
        for (int q = 0; q < 4; q++) { split2(pa[q], h0, l0); Ah[(size_t)ar*AST + ac + q] = h0; Al[(size_t)ar*AST + ac + q] = l0; }
        pa = (float*)&v1;
#pragma unroll
        for (int q = 0; q < 4; q++) { split2(pa[q], h0, l0); Ah[(size_t)(ar+32)*AST + ac + q] = h0; Al[(size_t)(ar+32)*AST + ac + q] = l0; }
#pragma unroll
        for (int i = 0; i < 4; i++) {
            int kr = br + i * 8;
            float4 w = *(const float4*)&W[(size_t)kr * 512 + col0 + bc];
            float* pw = (float*)&w;
#pragma unroll
            for (int q = 0; q < 4; q++) { split2(pw[q], h0, l0); Bh[(size_t)kr*BST + bc + q] = h0; Bl[(size_t)kr*BST + bc + q] = l0; }
        }
    }
    __syncthreads();

    for (int kt = 0; kt < 64; kt++) {
        int cur = kt & 1;
        float4 pa0, pa1, pwv[4];
        if (kt < 63) {
            int k0 = (kt + 1) * 32;
            pa0 = *(const float4*)&Abase[(size_t)ar * 2048 + k0 + ac];
            pa1 = *(const float4*)&Abase[(size_t)(ar + 32) * 2048 + k0 + ac];
#pragma unroll
            for (int i = 0; i < 4; i++)
                pwv[i] = *(const float4*)&W[(size_t)(k0 + br + i * 8) * 512 + col0 + bc];
        }
        const float* Ach = Ah + cur * 64 * AST;
        const float* Acl = Al + cur * 64 * AST;
        const float* Bch = Bh + cur * 32 * BST;
        const float* Bcl = Bl + cur * 32 * BST;
#pragma unroll
        for (int k8 = 0; k8 < 4; k8++) {
            int kb = k8 * 8;
            uint32_t afh[2][4], afl[2][4];
#pragma unroll
            for (int mm = 0; mm < 2; mm++) {
                int r0 = wm * 32 + mm * 16;
                afh[mm][0] = __float_as_uint(Ach[(size_t)(r0 + tg) * AST + kb + tig]);
                afh[mm][1] = __float_as_uint(Ach[(size_t)(r0 + tg + 8) * AST + kb + tig]);
                afh[mm][2] = __float_as_uint(Ach[(size_t)(r0 + tg) * AST + kb + tig + 4]);
                afh[mm][3] = __float_as_uint(Ach[(size_t)(r0 + tg + 8) * AST + kb + tig + 4]);
                afl[mm][0] = __float_as_uint(Acl[(size_t)(r0 + tg) * AST + kb + tig]);
                afl[mm][1] = __float_as_uint(Acl[(size_t)(r0 + tg + 8) * AST + kb + tig]);
                afl[mm][2] = __float_as_uint(Acl[(size_t)(r0 + tg) * AST + kb + tig + 4]);
                afl[mm][3] = __float_as_uint(Acl[(size_t)(r0 + tg + 8) * AST + kb + tig + 4]);
            }
#pragma unroll
            for (int nn = 0; nn < 4; nn++) {
                int n = wn * 32 + nn * 8 + tg;
                uint32_t bh0 = __float_as_uint(Bch[(size_t)(kb + tig) * BST + n]);
                uint32_t bh1 = __float_as_uint(Bch[(size_t)(kb + tig + 4) * BST + n]);
                uint32_t bl0 = __float_as_uint(Bcl[(size_t)(kb + tig) * BST + n]);
                uint32_t bl1 = __float_as_uint(Bcl[(size_t)(kb + tig + 4) * BST + n]);
#pragma unroll
                for (int mm = 0; mm < 2; mm++) {
                    mma8(acc[mm][nn][0], acc[mm][nn][1], acc[mm][nn][2], acc[mm][nn][3],
                         afh[mm][0], afh[mm][1], afh[mm][2], afh[mm][3], bh0, bh1);
                    mma8(acc[mm][nn][0], acc[mm][nn][1], acc[mm][nn][2], acc[mm][nn][3],
                         afh[mm][0], afh[mm][1], afh[mm][2], afh[mm][3], bl0, bl1);
                    mma8(acc[mm][nn][0], acc[mm][nn][1], acc[mm][nn][2], acc[mm][nn][3],
                         afl[mm][0], afl[mm][1], afl[mm][2], afl[mm][3], bh0, bh1);
                }
            }
        }
        if (kt < 63) {
            int nb = cur ^ 1;
            float h0, l0;
            float* p = (float*)&pa0;
#pragma unroll
            for (int q = 0; q < 4; q++) { split2(p[q], h0, l0); Ah[((size_t)nb*64 + ar)*AST + ac + q] = h0; Al[((size_t)nb*64 + ar)*AST + ac + q] = l0; }
            p = (float*)&pa1;
#pragma unroll
            for (int q = 0; q < 4; q++) { split2(p[q], h0, l0); Ah[((size_t)nb*64 + ar + 32)*AST + ac + q] = h0; Al[((size_t)nb*64 + ar + 32)*AST + ac + q] = l0; }
#pragma unroll
            for (int i = 0; i < 4; i++) {
                p = (float*)&pwv[i];
                int kr = nb * 32 + br + i * 8;
#pragma unroll
                for (int q = 0; q < 4; q++) { split2(p[q], h0, l0); Bh[(size_t)kr*BST + bc + q] = h0; Bl[(size_t)kr*BST + bc + q] = l0; }
            }
            __syncthreads();
        }
    }

#pragma unroll
    for (int mm = 0; mm < 2; mm++)
#pragma unroll
        for (int nn = 0; nn < 4; nn++) {
            int r = row0 + wm * 32 + mm * 16 + tg;
            int c = col0 + wn * 32 + nn * 8 + tig * 2;
#pragma unroll
            for (int h = 0; h < 2; h++) {
                int rr = r + h * 8;
                int bb = rr >> 7, tt = rr & 127;
                float v0 = acc[mm][nn][h * 2 + 0] + bias[c];
                float v1 = acc[mm][nn][h * 2 + 1] + bias[c + 1];
                v0 = v0 > 0.f ? v0 : 0.f;
                v1 = v1 > 0.f ? v1 : 0.f;
                *(float2*)&g_shareA[((size_t)tt * B + bb) * H + c] = make_float2(v0, v1);
            }
        }
}

// ---------------- group separation -> g_bufA [t][b][j][d] --------------------
__global__ __launch_bounds__(128) void k_groupsep(const float* __restrict__ feat,
                                                  const float* __restrict__ sepW,
                                                  const float* __restrict__ sepb) {
    int bt = blockIdx.x;          // b*T + t
    int b = bt >> 7, t = bt & 127;
    const float* fb = feat + (size_t)bt * (M * D);
    __shared__ float s_lg[M];
    int tid = threadIdx.x;
    int w = tid >> 5, lane = tid & 31;
    if (w < M) {
        float s = 0.f;
        for (int d = lane; d < D; d += 32) s += fb[w * D + d] * sepW[d];
#pragma unroll
        for (int o = 16; o; o >>= 1) s += __shfl_down_sync(0xffffffffu, s, o);
        if (lane == 0) s_lg[w] = s + sepb[0];
    }
    __syncthreads();
    float lg[M], mx = -1e30f;
#pragma unroll
    for (int m = 0; m < M; m++) { lg[m] = s_lg[m]; mx = fmaxf(mx, lg[m]); }
    float e[M], sum = 0.f;
#pragma unroll
    for (int m = 0; m < M; m++) { e[m] = expf(lg[m] - mx); sum += e[m]; }
    float sw[M], cnt0 = 0.f;
#pragma unroll
    for (int m = 0; m < M; m++) { sw[m] = (e[m] > 0.25f * sum) ? 1.f : 0.f; cnt0 += sw[m]; }
    float cnt1 = (float)M - cnt0;
    float inv0 = 1.f / (cnt0 + 1e-8f), inv1 = 1.f / (cnt1 + 1e-8f);
    float* o0 = g_bufA + ((size_t)t * B + b) * 2 * D;
    float* o1 = o0 + D;
    for (int d = tid; d < D; d += 128) {
        float s0 = 0.f, s1 = 0.f;
#pragma unroll
        for (int m = 0; m < M; m++) {
            float v = fb[m * D + d];
            s0 += sw[m] * v;
            s1 += (1.f - sw[m]) * v;
        }
        o0[d] = s0 * inv0;
        o1[d] = s1 * inv1;
    }
}

// ---------------- fused: finalize(t-1) + prep(t); one block per b ------------
__global__ __launch_bounds__(512) void k_step(const float* __restrict__ ctx,
                                              const float* __restrict__ archW,
                                              const float* __restrict__ archb,
                                              const float* __restrict__ bxp,
                                              const float* __restrict__ bhp,
                                              const float* __restrict__ bcp,
                                              int l, int t) {
    int b = blockIdx.x;
    int tid = threadIdx.x;
    const float* seq = l ? g_bufB : g_bufA;
    float* hid = l ? g_bufA : g_bufB;
    const float* shin = l ? g_shareB : g_shareA;
    float* shout = l ? g_shareA : g_shareB;

    __shared__ float s_h1[2][D];
    __shared__ float s_lg[2][K];
    __shared__ int s_sel[4];

    if (t == 0) {
        for (int i = tid; i < 2 * H; i += 512) g_cell[(size_t)b * 2 * H + i] = 0.f;
        for (int i = tid; i < H; i += 512) { g_shst[(size_t)b * H + i] = 0.f; g_cum[(size_t)b * H + i] = 0.f; }
        s_h1[0][tid] = 0.f;
        s_h1[1][tid] = 0.f;
    } else {
        int tp = t - 1;
        int p = tid;
        float sgsum = 0.f;
#pragma unroll
        for (int j = 0; j < 2; j++) {
            int k0 = g_sel[(b * 2 + j) * 2], k1 = g_sel[(b * 2 + j) * 2 + 1];
            float tot[5];
#pragma unroll
            for (int c = 0; c < 5; c++) {
                int f = c * 512 + p;
                size_t base = (size_t)(j * 64 + b) * F5H + f;
                float v = g_partial[base]
                        + g_partial[(size_t)1 * 128 * F5H + base]
                        + 0.5f * (g_partial[(size_t)(2 + k0) * 128 * F5H + base]
                                + g_partial[(size_t)(2 + k1) * 128 * F5H + base]);
                v += bxp[(size_t)(l * 2 + j) * F5H + f] + bhp[(size_t)(l * 2 + j) * F5H + f];
                v += 0.5f * (bcp[((size_t)(l * 2 + j) * K + k0) * F5H + f]
                           + bcp[((size_t)(l * 2 + j) * K + k1) * F5H + f]);
                tot[c] = v;
            }
            float ig = tot[0], fg = tot[1], og = tot[2], sg = tot[3], cc = tot[4];
            size_t ci = ((size_t)b * 2 + j) * H + p;
            float cell = g_cell[ci];
            float sf = 1.f / (1.f + expf(-fg));
            float si = 1.f / (1.f + expf(-ig));
            cell = (1.f - sf) * cell + si * tanhf(cc);
            g_cell[ci] = cell;
            float hv = (1.f / (1.f + expf(-og))) * tanhf(cell);
            hid[((size_t)tp * B + b) * 2 * H + (size_t)j * H + p] = hv;
            s_h1[j][p] = hv;
            sgsum += sg;
        }
        float gate = 1.f / (1.f + expf(-sgsum));
        size_t si = (size_t)b * H + p;
        float shf = shin[((size_t)tp * B + b) * H + p];
        float st = g_shst[si] + gate * shf;
        float cum = g_cum[si] + gate;
        g_shst[si] = st;
        g_cum[si] = cum;
        shout[((size_t)tp * B + b) * H + p] = st / cum;
    }
    if (t >= T) return;
    __syncthreads();

    int w = tid >> 5, lane = tid & 31;
    if (w < 12) {
        int j = w / K, k = w % K;
        const float* aW = archW + (size_t)l * H * K;
        float s = 0.f;
        for (int d = lane; d < D; d += 32) s += s_h1[j][d] * aW[(size_t)d * K + k];
#pragma unroll
        for (int o = 16; o; o >>= 1) s += __shfl_down_sync(0xffffffffu, s, o);
        if (lane == 0) s_lg[j][k] = s + archb[l * K + k];
    }
    __syncthreads();
    if (tid < 2) {
        int j = tid;
        int k0 = 0; float best = s_lg[j][0];
        for (int k = 1; k < K; k++) if (s_lg[j][k] > best) { best = s_lg[j][k]; k0 = k; }
        int k1 = -1; float b2 = 0.f;
        for (int k = 0; k < K; k++) {
            if (k == k0) continue;
            if (k1 < 0 || s_lg[j][k] > b2) { b2 = s_lg[j][k]; k1 = k; }
        }
        s_sel[j * 2] = k0; s_sel[j * 2 + 1] = k1;
        g_sel[(b * 2 + j) * 2] = k0;
        g_sel[(b * 2 + j) * 2 + 1] = k1;
    }

    const float* seq_t  = seq + ((size_t)t * B + b) * 2 * D;
    const float* seq_n  = (t + 1 < T) ? seq + ((size_t)(t + 1) * B + b) * 2 * D : 0;
    const float* h_prev2 = (t >= 2) ? hid + ((size_t)(t - 2) * B + b) * 2 * D : 0;
    const float* sc = ctx + ((size_t)b * T + t) * H;

    // unmasked concat row, pre-split (hi,lo): chunks: 0=x_t, 1=h1, 2..7=cand
    for (int idx = tid; idx < 2 * 4096; idx += 512) {
        int j = idx >> 12;
        int q = idx & 4095;
        int c = q >> 9;
        int d = q & 511;
        float v;
        if (c == 0) v = seq_t[j * D + d];
        else if (c == 1) v = s_h1[j][d];
        else {
            int k = c - 2;
            if (k == 0)      v = h_prev2 ? h_prev2[j * D + d] : 0.f;
            else if (k == 1) v = seq_n ? seq_n[j * D + d] : 0.f;
            else if (k == 2) v = s_h1[1 - j][d];
            else if (k == 3) v = seq_t[(1 - j) * D + d];
            else if (k == 4) v = seq_n ? seq_n[(1 - j) * D + d] : 0.f;
            else             v = sc[d];
        }
        float hi, lo;
        split2(v, hi, lo);
        g_A[(size_t)(j * 64 + b) * 4096 + q] = make_float2(hi, lo);
    }
}

// ---------------- per-step 3xtf32 GEMM, packed fragment layouts --------------
// grid (20 cols, 2 j, 16 z): z<4 fixed chunks, z>=4 candidate gather.
// block tile 32 rows x 128 cols, kt=16, warp tile 16x32.
__global__ __launch_bounds__(256) void k_gemm(const float* __restrict__ Wx,
                                              const float* __restrict__ Wh,
                                              const float* __restrict__ Wc,
                                              int l) {
    int col0 = blockIdx.x * 128;
    int j = blockIdx.y;
    int z = blockIdx.z;
    int tid = threadIdx.x;
    int warp = tid >> 5, lane = tid & 31;

    __shared__ int s_list[32];
    __shared__ int s_cnt;
    __shared__ unsigned s_mask[2];

    int ks, tile;
    if (z < 4) { ks = z >> 1; tile = z & 1; }
    else       { ks = 2 + ((z - 4) >> 1); tile = (z - 4) & 1; }

    if (z < 4) {
        if (tid < 32) s_list[tid] = tile * 32 + tid;
        if (tid == 0) s_cnt = 64;
    } else {
        int k = ks - 2;
        if (tid < 32) s_list[tid] = -1;
        if (warp < 2) {
            int b = warp * 32 + lane;
            int s0 = g_sel[(b * 2 + j) * 2];
            int s1 = g_sel[(b * 2 + j) * 2 + 1];
            bool f = (s0 == k) || (s1 == k);
            unsigned m = __ballot_sync(0xffffffffu, f);
            if (lane == 0) s_mask[warp] = m;
        }
        __syncthreads();
        unsigned m0 = s_mask[0], m1 = s_mask[1];
        if (tid == 0) s_cnt = __popc(m0) + __popc(m1);
        if (warp < 2) {
            unsigned m = warp ? m1 : m0;
            if ((m >> lane) & 1u) {
                int pos = (warp ? __popc(m0) : 0) + __popc(m & ((1u << lane) - 1u));
                int p = pos - tile * 32;
                if (p >= 0 && p < 32) s_list[p] = warp * 32 + lane;
            }
        }
    }
    __syncthreads();
    if (tile * 32 >= s_cnt) return;

    const float* Wb;
    if (ks == 0)      Wb = Wx + (size_t)(l * 2 + j) * D * F5H;
    else if (ks == 1) Wb = Wh + (size_t)(l * 2 + j) * H * F5H;
    else              Wb = Wc + ((size_t)(l * 2 + j) * K + (ks - 2)) * (size_t)D * F5H;
    int chunkoff = ks * 512;

    extern __shared__ float4 sm4[];
    float4* Af = sm4;          // [s][k8 2][wm 2][hl 2][lane 32]
    float4* Bf = sm4 + 512;    // [s][k8 2][tig 4][n 128 pad 130]

    int wm = warp >> 2, wn = warp & 3;
    int tg = lane >> 2, tig = lane & 3;

    // A copy roles (tid < 128)
    int a_k8 = tid >> 6, a_wm = (tid >> 5) & 1, a_lane = tid & 31;
    int a_tg = a_lane >> 2, a_tig = a_lane & 3;
    int arA = 0, arB = 0;
    if (tid < 128) {
        arA = s_list[a_wm * 16 + a_tg];     if (arA < 0) arA = 0;
        arB = s_list[a_wm * 16 + a_tg + 8]; if (arB < 0) arB = 0;
    }
    const float2* gA = g_A + (size_t)j * 64 * 4096 + chunkoff;

    // B copy roles (all 256)
    int b_k8 = tid >> 7, b_tig = (tid >> 5) & 3, b_n0 = (tid & 31) * 4;

    float acc[4][4];
#pragma unroll
    for (int a = 0; a < 4; a++)
#pragma unroll
        for (int c = 0; c < 4; c++) acc[a][c] = 0.f;

    // ---- prologue: stage 0 ----
    {
        if (tid < 128) {
            int k = a_k8 * 8 + a_tig;
            float2 A0 = gA[(size_t)arA * 4096 + k];
            float2 B0 = gA[(size_t)arB * 4096 + k];
            float2 A4 = gA[(size_t)arA * 4096 + k + 4];
            float2 B4 = gA[(size_t)arB * 4096 + k + 4];
            Af[(((0 * 2 + a_k8) * 2 + a_wm) * 2 + 0) * 32 + a_lane] = make_float4(A0.x, B0.x, A4.x, B4.x);
            Af[(((0 * 2 + a_k8) * 2 + a_wm) * 2 + 1) * 32 + a_lane] = make_float4(A0.y, B0.y, A4.y, B4.y);
        }
        int k = b_k8 * 8 + b_tig;
        float4 w0 = *(const float4*)&Wb[(size_t)k * F5H + col0 + b_n0];
        float4 w4 = *(const float4*)&Wb[(size_t)(k + 4) * F5H + col0 + b_n0];
        float* p0 = (float*)&w0;
        float* p4 = (float*)&w4;
        float4* dst = &Bf[((0 * 2 + b_k8) * 4 + b_tig) * 130 + b_n0];
#pragma unroll
        for (int i = 0; i < 4; i++) {
            float h0, l0, h4, l4;
            split2(p0[i], h0, l0);
            split2(p4[i], h4, l4);
            dst[i] = make_float4(h0, h4, l0, l4);
        }
    }
    __syncthreads();

    // ---- main loop: 32 kt tiles of 16 K ----
    for (int kt = 0; kt < 32; kt++) {
        int cur = kt & 1;
        // prefetch next stage into registers
        float2 pA0, pB0, pA4, pB4;
        float4 pw0, pw4;
        if (kt < 31) {
            int kb = (kt + 1) * 16;
            if (tid < 128) {
                int k = kb + a_k8 * 8 + a_tig;
                pA0 = gA[(size_t)arA * 4096 + k];
                pB0 = gA[(size_t)arB * 4096 + k];
                pA4 = gA[(size_t)arA * 4096 + k + 4];
                pB4 = gA[(size_t)arB * 4096 + k + 4];
            }
            int k = kb + b_k8 * 8 + b_tig;
            pw0 = *(const float4*)&Wb[(size_t)k * F5H + col0 + b_n0];
            pw4 = *(const float4*)&Wb[(size_t)(k + 4) * F5H + col0 + b_n0];
        }
        // compute on current stage
#pragma unroll
        for (int k8 = 0; k8 < 2; k8++) {
            float4 ah = Af[(((cur * 2 + k8) * 2 + wm) * 2 + 0) * 32 + lane];
            float4 al = Af[(((cur * 2 + k8) * 2 + wm) * 2 + 1) * 32 + lane];
            uint32_t ah0 = __float_as_uint(ah.x), ah1 = __float_as_uint(ah.y);
            uint32_t ah2 = __float_as_uint(ah.z), ah3 = __float_as_uint(ah.w);
            uint32_t al0 = __float_as_uint(al.x), al1 = __float_as_uint(al.y);
            uint32_t al2 = __float_as_uint(al.z), al3 = __float_as_uint(al.w);
#pragma unroll
            for (int nn = 0; nn < 4; nn++) {
                float4 bb = Bf[((cur * 2 + k8) * 4 + tig) * 130 + wn * 32 + nn * 8 + tg];
                uint32_t bh0 = __float_as_uint(bb.x), bh1 = __float_as_uint(bb.y);
                uint32_t bl0 = __float_as_uint(bb.z), bl1 = __float_as_uint(bb.w);
                mma8(acc[nn][0], acc[nn][1], acc[nn][2], acc[nn][3],
                     ah0, ah1, ah2, ah3, bh0, bh1);
                mma8(acc[nn][0], acc[nn][1], acc[nn][2], acc[nn][3],
                     ah0, ah1, ah2, ah3, bl0, bl1);
                mma8(acc[nn][0], acc[nn][1], acc[nn][2], acc[nn][3],
                     al0, al1, al2, al3, bh0, bh1);
            }
        }
        // store next stage
        if (kt < 31) {
            int nb = cur ^ 1;
            if (tid < 128) {
                Af[(((nb * 2 + a_k8) * 2 + a_wm) * 2 + 0) * 32 + a_lane] = make_float4(pA0.x, pB0.x, pA4.x, pB4.x);
                Af[(((nb * 2 + a_k8) * 2 + a_wm) * 2 + 1) * 32 + a_lane] = make_float4(pA0.y, pB0.y, pA4.y, pB4.y);
            }
            float* p0 = (float*)&pw0;
            float* p4 = (float*)&pw4;
            float4* dst = &Bf[((nb * 2 + b_k8) * 4 + b_tig) * 130 + b_n0];
#pragma unroll
            for (int i = 0; i < 4; i++) {
                float h0, l0, h4, l4;
                split2(p0[i], h0, l0);
                split2(p4[i], h4, l4);
                dst[i] = make_float4(h0, h4, l0, l4);
            }
            __syncthreads();
        }
    }

    float* outp = g_partial + (size_t)ks * 128 * F5H;
    int rlo = s_list[wm * 16 + tg];
    int rhi = s_list[wm * 16 + tg + 8];
#pragma unroll
    for (int nn = 0; nn < 4; nn++) {
        int c = col0 + wn * 32 + nn * 8 + tig * 2;
        if (rlo >= 0)
            *(float2*)&outp[(size_t)(j * 64 + rlo) * F5H + c] = make_float2(acc[nn][0], acc[nn][1]);
        if (rhi >= 0)
            *(float2*)&outp[(size_t)(j * 64 + rhi) * F5H + c] = make_float2(acc[nn][2], acc[nn][3]);
    }
}

// ---------------- output assembly -------------------------------------------
__global__ void k_output(float* __restrict__ out) {
    size_t i = (size_t)blockIdx.x * 256 + threadIdx.x;
    size_t total = (size_t)B * T * 1536;
    if (i >= total) return;
    int c = (int)(i % 1536);
    size_t bt = i / 1536;
    int b = (int)(bt >> 7), t = (int)(bt & 127);
    float v;
    if (c < 1024) {
        size_t idx = ((size_t)t * B + b) * 1024 + c;
        v = 0.5f * (g_bufB[idx] + g_bufA[idx]);
    } else {
        int p = c - 1024;
        size_t idx = ((size_t)t * B + b) * H + p;
        v = 0.5f * (g_shareB[idx] + g_shareA[idx]);
    }
    out[i] = v;
}

// ---------------- launch ------------------------------------------------------
extern "C" void kernel_launch(void* const* d_in, const int* in_sizes, int n_in,
                              void* d_out, int out_size) {
    const float* feat = (const float*)d_in[0];
    const float* ctx  = (const float*)d_in[1];
    const float* l2sW = (const float*)d_in[2];
    const float* l2sb = (const float*)d_in[3];
    const float* sepW = (const float*)d_in[4];
    const float* sepb = (const float*)d_in[5];
    const float* aW   = (const float*)d_in[6];
    const float* ab   = (const float*)d_in[7];
    const float* Wx   = (const float*)d_in[8];
    const float* bx   = (const float*)d_in[9];
    const float* Wh   = (const float*)d_in[10];
    const float* bh   = (const float*)d_in[11];
    const float* Wc   = (const float*)d_in[12];
    const float* bc   = (const float*)d_in[13];
    float* out = (float*)d_out;

    cudaFuncSetAttribute(k_share, cudaFuncAttributeMaxDynamicSharedMemorySize, SMEM_S);
    cudaFuncSetAttribute(k_gemm, cudaFuncAttributeMaxDynamicSharedMemorySize, SMEM_G);

    k_share<<<dim3(4, 128), 256, SMEM_S>>>(feat, l2sW, l2sb);
    k_groupsep<<<B * T, 128>>>(feat, sepW, sepb);
    for (int l = 0; l < LNUM; l++) {
        for (int t = 0; t < T; t++) {
            k_step<<<B, 512>>>(ctx, aW, ab, bx, bh, bc, l, t);
            k_gemm<<<dim3(20, 2, 16), 256, SMEM_G>>>(Wx, Wh, Wc, l);
        }
        k_step<<<B, 512>>>(ctx, aW, ab, bx, bh, bc, l, T);
    }
    k_output<<<(int)(((size_t)B * T * 1536 + 255) / 256), 256>>>(out);
}

// round 9
// speedup vs baseline: 1.1107x; 1.1107x over previous
#include <cuda_runtime.h>
#include <math.h>
#include <stdint.h>

#define B 64
#define T 128
#define M 4
#define D 512
#define H 512
#define LNUM 2
#define K 6
#define F5H 2560   // 5*H

#define AST 36     // k_share A smem row stride
#define BST 136    // k_share B smem row stride
#define SMEM_S ((2*64*AST*2 + 2*32*BST*2) * 4)

// k_gemm: Af [2][16][34] float4 + Bf [2][16][130] float4
#define SMEM_G ((2*16*34 + 2*16*130) * 16)

// ---------------- persistent scratch ----------------------------------------
__device__ float g_bufA[(size_t)T * B * 2 * D];
__device__ float g_bufB[(size_t)T * B * 2 * D];
__device__ float g_shareA[(size_t)T * B * H];
__device__ float g_shareB[(size_t)T * B * H];
// A rows pre-split & pair-packed: [row 128][pi 2048] = (hi(k),hi(k+4),lo(k),lo(k+4))
// pi = chunk*256 + kt*16 + k8*4 + tig ; k = chunk*512 + kt*32 + k8*8 + tig
__device__ float4 g_Apk[(size_t)128 * 2048];
__device__ float g_partial[(size_t)8 * 128 * F5H];
__device__ float g_cell[(size_t)B * 2 * H];
__device__ float g_shst[(size_t)B * H];
__device__ float g_cum[(size_t)B * H];
__device__ int   g_sel[B * 2 * 2];

__device__ __forceinline__ float to_tf32(float x) {
    float r; asm("cvt.rna.tf32.f32 %0, %1;" : "=f"(r) : "f"(x)); return r;
}
__device__ __forceinline__ void split2(float x, float& hi, float& lo) {
    hi = to_tf32(x);
    lo = to_tf32(x - hi);
}

__device__ __forceinline__ void mma8(float& c0, float& c1, float& c2, float& c3,
                                     uint32_t a0, uint32_t a1, uint32_t a2, uint32_t a3,
                                     uint32_t b0, uint32_t b1) {
    asm volatile("mma.sync.aligned.m16n8k8.row.col.f32.tf32.tf32.f32 "
                 "{%0,%1,%2,%3}, {%4,%5,%6,%7}, {%8,%9}, {%0,%1,%2,%3};"
                 : "+f"(c0), "+f"(c1), "+f"(c2), "+f"(c3)
                 : "r"(a0), "r"(a1), "r"(a2), "r"(a3), "r"(b0), "r"(b1));
}

// ---------------- 3xtf32 share GEMM: [8192,2048]@[2048,512]+bias+relu --------
__global__ __launch_bounds__(256) void k_share(const float* __restrict__ feat,
                                               const float* __restrict__ W,
                                               const float* __restrict__ bias) {
    int col0 = blockIdx.x * 128;
    int row0 = blockIdx.y * 64;
    const float* Abase = feat + (size_t)row0 * 2048;

    extern __shared__ float sm[];
    float* Ah = sm;
    float* Al = Ah + 2 * 64 * AST;
    float* Bh = Al + 2 * 64 * AST;
    float* Bl = Bh + 2 * 32 * BST;

    int tid = threadIdx.x;
    int warp = tid >> 5, lane = tid & 31;
    int wm = warp >> 2, wn = warp & 3;
    int tg = lane >> 2, tig = lane & 3;
    int ar = tid >> 3, ac = (tid & 7) * 4;
    int br = warp, bc = lane * 4;

    float acc[2][4][4];
#pragma unroll
    for (int a = 0; a < 2; a++)
#pragma unroll
        for (int b = 0; b < 4; b++)
#pragma unroll
            for (int c = 0; c < 4; c++) acc[a][b][c] = 0.f;

    {
        float4 v0 = *(const float4*)&Abase[(size_t)ar * 2048 + ac];
        float4 v1 = *(const float4*)&Abase[(size_t)(ar + 32) * 2048 + ac];
        float h0, l0;
        float* pa = (float*)&v0;
#pragma unroll
        for (int q = 0; q < 4; q++) { split2(pa[q], h0, l0); Ah[(size_t)ar*AST + ac + q] = h0; Al[(size_t)ar*AST + ac + q] = l0; }
        pa = (float*)&v1;
#pragma unroll
        for (int q = 0; q < 4; q++) { split2(pa[q], h0, l0); Ah[(size_t)(ar+32)*AST + ac + q] = h0; Al[(size_t)(ar+32)*AST + ac + q] = l0; }
#pragma unroll
        for (int i = 0; i < 4; i++) {
            int kr = br + i * 8;
            float4 w = *(const float4*)&W[(size_t)kr * 512 + col0 + bc];
            float* pw = (float*)&w;
#pragma unroll
            for (int q = 0; q < 4; q++) { split2(pw[q], h0, l0); Bh[(size_t)kr*BST + bc + q] = h0; Bl[(size_t)kr*BST + bc + q] = l0; }
        }
    }
    __syncthreads();

    for (int kt = 0; kt < 64; kt++) {
        int cur = kt & 1;
        float4 pa0, pa1, pwv[4];
        if (kt < 63) {
            int k0 = (kt + 1) * 32;
            pa0 = *(const float4*)&Abase[(size_t)ar * 2048 + k0 + ac];
            pa1 = *(const float4*)&Abase[(size_t)(ar + 32) * 2048 + k0 + ac];
#pragma unroll
            for (int i = 0; i < 4; i++)
                pwv[i] = *(const float4*)&W[(size_t)(k0 + br + i * 8) * 512 + col0 + bc];
        }
        const float* Ach = Ah + cur * 64 * AST;
        const float* Acl = Al + cur * 64 * AST;
        const float* Bch = Bh + cur * 32 * BST;
        const float* Bcl = Bl + cur * 32 * BST;
#pragma unroll
        for (int k8 = 0; k8 < 4; k8++) {
            int kb = k8 * 8;
            uint32_t afh[2][4], afl[2][4];
#pragma unroll
            for (int mm = 0; mm < 2; mm++) {
                int r0 = wm * 32 + mm * 16;
                afh[mm][0] = __float_as_uint(Ach[(size_t)(r0 + tg) * AST + kb + tig]);
                afh[mm][1] = __float_as_uint(Ach[(size_t)(r0 + tg + 8) * AST + kb + tig]);
                afh[mm][2] = __float_as_uint(Ach[(size_t)(r0 + tg) * AST + kb + tig + 4]);
                afh[mm][3] = __float_as_uint(Ach[(size_t)(r0 + tg + 8) * AST + kb + tig + 4]);
                afl[mm][0] = __float_as_uint(Acl[(size_t)(r0 + tg) * AST + kb + tig]);
                afl[mm][1] = __float_as_uint(Acl[(size_t)(r0 + tg + 8) * AST + kb + tig]);
                afl[mm][2] = __float_as_uint(Acl[(size_t)(r0 + tg) * AST + kb + tig + 4]);
                afl[mm][3] = __float_as_uint(Acl[(size_t)(r0 + tg + 8) * AST + kb + tig + 4]);
            }
#pragma unroll
            for (int nn = 0; nn < 4; nn++) {
                int n = wn * 32 + nn * 8 + tg;
                uint32_t bh0 = __float_as_uint(Bch[(size_t)(kb + tig) * BST + n]);
                uint32_t bh1 = __float_as_uint(Bch[(size_t)(kb + tig + 4) * BST + n]);
                uint32_t bl0 = __float_as_uint(Bcl[(size_t)(kb + tig) * BST + n]);
                uint32_t bl1 = __float_as_uint(Bcl[(size_t)(kb + tig + 4) * BST + n]);
#pragma unroll
                for (int mm = 0; mm < 2; mm++) {
                    mma8(acc[mm][nn][0], acc[mm][nn][1], acc[mm][nn][2], acc[mm][nn][3],
                         afh[mm][0], afh[mm][1], afh[mm][2], afh[mm][3], bh0, bh1);
                    mma8(acc[mm][nn][0], acc[mm][nn][1], acc[mm][nn][2], acc[mm][nn][3],
                         afh[mm][0], afh[mm][1], afh[mm][2], afh[mm][3], bl0, bl1);
                    mma8(acc[mm][nn][0], acc[mm][nn][1], acc[mm][nn][2], acc[mm][nn][3],
                         afl[mm][0], afl[mm][1], afl[mm][2], afl[mm][3], bh0, bh1);
                }
            }
        }
        if (kt < 63) {
            int nb = cur ^ 1;
            float h0, l0;
            float* p = (float*)&pa0;
#pragma unroll
            for (int q = 0; q < 4; q++) { split2(p[q], h0, l0); Ah[((size_t)nb*64 + ar)*AST + ac + q] = h0; Al[((size_t)nb*64 + ar)*AST + ac + q] = l0; }
            p = (float*)&pa1;
#pragma unroll
            for (int q = 0; q < 4; q++) { split2(p[q], h0, l0); Ah[((size_t)nb*64 + ar + 32)*AST + ac + q] = h0; Al[((size_t)nb*64 + ar + 32)*AST + ac + q] = l0; }
#pragma unroll
            for (int i = 0; i < 4; i++) {
                p = (float*)&pwv[i];
                int kr = nb * 32 + br + i * 8;
#pragma unroll
                for (int q = 0; q < 4; q++) { split2(p[q], h0, l0); Bh[(size_t)kr*BST + bc + q] = h0; Bl[(size_t)kr*BST + bc + q] = l0; }
            }
            __syncthreads();
        }
    }

#pragma unroll
    for (int mm = 0; mm < 2; mm++)
#pragma unroll
        for (int nn = 0; nn < 4; nn++) {
            int r = row0 + wm * 32 + mm * 16 + tg;
            int c = col0 + wn * 32 + nn * 8 + tig * 2;
#pragma unroll
            for (int h = 0; h < 2; h++) {
                int rr = r + h * 8;
                int bb = rr >> 7, tt = rr & 127;
                float v0 = acc[mm][nn][h * 2 + 0] + bias[c];
                float v1 = acc[mm][nn][h * 2 + 1] + bias[c + 1];
                v0 = v0 > 0.f ? v0 : 0.f;
                v1 = v1 > 0.f ? v1 : 0.f;
                *(float2*)&g_shareA[((size_t)tt * B + bb) * H + c] = make_float2(v0, v1);
            }
        }
}

// ---------------- group separation -> g_bufA [t][b][j][d] --------------------
__global__ __launch_bounds__(128) void k_groupsep(const float* __restrict__ feat,
                                                  const float* __restrict__ sepW,
                                                  const float* __restrict__ sepb) {
    int bt = blockIdx.x;          // b*T + t
    int b = bt >> 7, t = bt & 127;
    const float* fb = feat + (size_t)bt * (M * D);
    __shared__ float s_lg[M];
    int tid = threadIdx.x;
    int w = tid >> 5, lane = tid & 31;
    if (w < M) {
        float s = 0.f;
        for (int d = lane; d < D; d += 32) s += fb[w * D + d] * sepW[d];
#pragma unroll
        for (int o = 16; o; o >>= 1) s += __shfl_down_sync(0xffffffffu, s, o);
        if (lane == 0) s_lg[w] = s + sepb[0];
    }
    __syncthreads();
    float lg[M], mx = -1e30f;
#pragma unroll
    for (int m = 0; m < M; m++) { lg[m] = s_lg[m]; mx = fmaxf(mx, lg[m]); }
    float e[M], sum = 0.f;
#pragma unroll
    for (int m = 0; m < M; m++) { e[m] = expf(lg[m] - mx); sum += e[m]; }
    float sw[M], cnt0 = 0.f;
#pragma unroll
    for (int m = 0; m < M; m++) { sw[m] = (e[m] > 0.25f * sum) ? 1.f : 0.f; cnt0 += sw[m]; }
    float cnt1 = (float)M - cnt0;
    float inv0 = 1.f / (cnt0 + 1e-8f), inv1 = 1.f / (cnt1 + 1e-8f);
    float* o0 = g_bufA + ((size_t)t * B + b) * 2 * D;
    float* o1 = o0 + D;
    for (int d = tid; d < D; d += 128) {
        float s0 = 0.f, s1 = 0.f;
#pragma unroll
        for (int m = 0; m < M; m++) {
            float v = fb[m * D + d];
            s0 += sw[m] * v;
            s1 += (1.f - sw[m]) * v;
        }
        o0[d] = s0 * inv0;
        o1[d] = s1 * inv1;
    }
}

// ---------------- fused: finalize(t-1) + prep(t); one block per b ------------
__global__ __launch_bounds__(512) void k_step(const float* __restrict__ ctx,
                                              const float* __restrict__ archW,
                                              const float* __restrict__ archb,
                                              const float* __restrict__ bxp,
                                              const float* __restrict__ bhp,
                                              const float* __restrict__ bcp,
                                              int l, int t) {
    int b = blockIdx.x;
    int tid = threadIdx.x;
    const float* seq = l ? g_bufB : g_bufA;
    float* hid = l ? g_bufA : g_bufB;
    const float* shin = l ? g_shareB : g_shareA;
    float* shout = l ? g_shareA : g_shareB;

    __shared__ float s_h1[2][D];
    __shared__ float s_lg[2][K];
    __shared__ int s_sel[4];

    if (t == 0) {
        for (int i = tid; i < 2 * H; i += 512) g_cell[(size_t)b * 2 * H + i] = 0.f;
        for (int i = tid; i < H; i += 512) { g_shst[(size_t)b * H + i] = 0.f; g_cum[(size_t)b * H + i] = 0.f; }
        s_h1[0][tid] = 0.f;
        s_h1[1][tid] = 0.f;
    } else {
        int tp = t - 1;
        int p = tid;
        float sgsum = 0.f;
#pragma unroll
        for (int j = 0; j < 2; j++) {
            int k0 = g_sel[(b * 2 + j) * 2], k1 = g_sel[(b * 2 + j) * 2 + 1];
            float tot[5];
#pragma unroll
            for (int c = 0; c < 5; c++) {
                int f = c * 512 + p;
                size_t base = (size_t)(j * 64 + b) * F5H + f;
                float v = g_partial[base]
                        + g_partial[(size_t)1 * 128 * F5H + base]
                        + 0.5f * (g_partial[(size_t)(2 + k0) * 128 * F5H + base]
                                + g_partial[(size_t)(2 + k1) * 128 * F5H + base]);
                v += bxp[(size_t)(l * 2 + j) * F5H + f] + bhp[(size_t)(l * 2 + j) * F5H + f];
                v += 0.5f * (bcp[((size_t)(l * 2 + j) * K + k0) * F5H + f]
                           + bcp[((size_t)(l * 2 + j) * K + k1) * F5H + f]);
                tot[c] = v;
            }
            float ig = tot[0], fg = tot[1], og = tot[2], sg = tot[3], cc = tot[4];
            size_t ci = ((size_t)b * 2 + j) * H + p;
            float cell = g_cell[ci];
            float sf = 1.f / (1.f + expf(-fg));
            float si = 1.f / (1.f + expf(-ig));
            cell = (1.f - sf) * cell + si * tanhf(cc);
            g_cell[ci] = cell;
            float hv = (1.f / (1.f + expf(-og))) * tanhf(cell);
            hid[((size_t)tp * B + b) * 2 * H + (size_t)j * H + p] = hv;
            s_h1[j][p] = hv;
            sgsum += sg;
        }
        float gate = 1.f / (1.f + expf(-sgsum));
        size_t si = (size_t)b * H + p;
        float shf = shin[((size_t)tp * B + b) * H + p];
        float st = g_shst[si] + gate * shf;
        float cum = g_cum[si] + gate;
        g_shst[si] = st;
        g_cum[si] = cum;
        shout[((size_t)tp * B + b) * H + p] = st / cum;
    }
    if (t >= T) return;
    __syncthreads();

    int w = tid >> 5, lane = tid & 31;
    if (w < 12) {
        int j = w / K, k = w % K;
        const float* aW = archW + (size_t)l * H * K;
        float s = 0.f;
        for (int d = lane; d < D; d += 32) s += s_h1[j][d] * aW[(size_t)d * K + k];
#pragma unroll
        for (int o = 16; o; o >>= 1) s += __shfl_down_sync(0xffffffffu, s, o);
        if (lane == 0) s_lg[j][k] = s + archb[l * K + k];
    }
    __syncthreads();
    if (tid < 2) {
        int j = tid;
        int k0 = 0; float best = s_lg[j][0];
        for (int k = 1; k < K; k++) if (s_lg[j][k] > best) { best = s_lg[j][k]; k0 = k; }
        int k1 = -1; float b2 = 0.f;
        for (int k = 0; k < K; k++) {
            if (k == k0) continue;
            if (k1 < 0 || s_lg[j][k] > b2) { b2 = s_lg[j][k]; k1 = k; }
        }
        s_sel[j * 2] = k0; s_sel[j * 2 + 1] = k1;
        g_sel[(b * 2 + j) * 2] = k0;
        g_sel[(b * 2 + j) * 2 + 1] = k1;
    }

    const float* seq_t  = seq + ((size_t)t * B + b) * 2 * D;
    const float* seq_n  = (t + 1 < T) ? seq + ((size_t)(t + 1) * B + b) * 2 * D : 0;
    const float* h_prev2 = (t >= 2) ? hid + ((size_t)(t - 2) * B + b) * 2 * D : 0;
    const float* sc = ctx + ((size_t)b * T + t) * H;

    // unmasked concat row, split + pair-packed:
    // pi = chunk*256 + kt*16 + k8*4 + tig -> k = chunk*512 + kt*32 + k8*8 + tig (+4)
    for (int idx = tid; idx < 2 * 2048; idx += 512) {
        int j = idx >> 11;
        int pi = idx & 2047;
        int c = pi >> 8;
        int r = pi & 255;
        int kt = r >> 4, rr = r & 15;
        int kin = kt * 32 + (rr >> 2) * 8 + (rr & 3);
        float vv[2];
#pragma unroll
        for (int hh = 0; hh < 2; hh++) {
            int d = kin + hh * 4;
            float v;
            if (c == 0) v = seq_t[j * D + d];
            else if (c == 1) v = s_h1[j][d];
            else {
                int k = c - 2;
                if (k == 0)      v = h_prev2 ? h_prev2[j * D + d] : 0.f;
                else if (k == 1) v = seq_n ? seq_n[j * D + d] : 0.f;
                else if (k == 2) v = s_h1[1 - j][d];
                else if (k == 3) v = seq_t[(1 - j) * D + d];
                else if (k == 4) v = seq_n ? seq_n[(1 - j) * D + d] : 0.f;
                else             v = sc[d];
            }
            vv[hh] = v;
        }
        float h0, l0, h4, l4;
        split2(vv[0], h0, l0);
        split2(vv[1], h4, l4);
        g_Apk[(size_t)(j * 64 + b) * 2048 + pi] = make_float4(h0, h4, l0, l4);
    }
}

// ---------------- per-step 3xtf32 GEMM, packed pair layouts ------------------
// grid (20 cols, 2 j, 16 z): z<4 fixed chunks, z>=4 candidate gather.
// block 32 rows x 128 cols, 16 stages of 32 K, warp tile 16x32 (wm 2 x wn 4).
__global__ __launch_bounds__(256) void k_gemm(const float* __restrict__ Wx,
                                              const float* __restrict__ Wh,
                                              const float* __restrict__ Wc,
                                              int l) {
    int col0 = blockIdx.x * 128;
    int j = blockIdx.y;
    int z = blockIdx.z;
    int tid = threadIdx.x;
    int warp = tid >> 5, lane = tid & 31;

    __shared__ int s_list[32];
    __shared__ int s_cnt;
    __shared__ unsigned s_mask[2];

    int ks, tile;
    if (z < 4) { ks = z >> 1; tile = z & 1; }
    else       { ks = 2 + ((z - 4) >> 1); tile = (z - 4) & 1; }

    if (z < 4) {
        if (tid < 32) s_list[tid] = tile * 32 + tid;
        if (tid == 0) s_cnt = 64;
    } else {
        int k = ks - 2;
        if (tid < 32) s_list[tid] = -1;
        if (warp < 2) {
            int b = warp * 32 + lane;
            int s0 = g_sel[(b * 2 + j) * 2];
            int s1 = g_sel[(b * 2 + j) * 2 + 1];
            bool f = (s0 == k) || (s1 == k);
            unsigned m = __ballot_sync(0xffffffffu, f);
            if (lane == 0) s_mask[warp] = m;
        }
        __syncthreads();
        unsigned m0 = s_mask[0], m1 = s_mask[1];
        if (tid == 0) s_cnt = __popc(m0) + __popc(m1);
        if (warp < 2) {
            unsigned m = warp ? m1 : m0;
            if ((m >> lane) & 1u) {
                int pos = (warp ? __popc(m0) : 0) + __popc(m & ((1u << lane) - 1u));
                int p = pos - tile * 32;
                if (p >= 0 && p < 32) s_list[p] = warp * 32 + lane;
            }
        }
    }
    __syncthreads();
    if (tile * 32 >= s_cnt) return;

    const float* Wb;
    if (ks == 0)      Wb = Wx + (size_t)(l * 2 + j) * D * F5H;
    else if (ks == 1) Wb = Wh + (size_t)(l * 2 + j) * H * F5H;
    else              Wb = Wc + ((size_t)(l * 2 + j) * K + (ks - 2)) * (size_t)D * F5H;

    extern __shared__ float4 sm4[];
    float4* Af = sm4;            // [2][16 pr][34]
    float4* Bf = sm4 + 2 * 544;  // [2][16 pr][130]

    int wm = warp >> 3, wn = warp & 3;         // 8 warps: wm = warp>>2? see below
    // 8 warps as (wm 2) x (wn 4):
    wm = warp >> 2; wn = warp & 3;
    int tg = lane >> 2, tig = lane & 3;

    // copy roles
    int c_pr = tid >> 4;          // 0..15 : pair-row
    int c_ri = tid & 15;          // A: row index; B: n lane
    int rowA = s_list[c_ri];      if (rowA < 0) rowA = 0;
    int rowB = s_list[c_ri + 16]; if (rowB < 0) rowB = 0;
    const float4* Apk = g_Apk + (size_t)j * 64 * 2048 + ks * 256;
    int b_k = (c_pr >> 2) * 8 + (c_pr & 3);    // k within stage for this pair-row

    float acc[4][4];
#pragma unroll
    for (int a = 0; a < 4; a++)
#pragma unroll
        for (int c = 0; c < 4; c++) acc[a][c] = 0.f;

    // ---- prologue: stage 0 ----
    {
        Af[c_pr * 34 + c_ri]      = Apk[(size_t)rowA * 2048 + c_pr];
        Af[c_pr * 34 + c_ri + 16] = Apk[(size_t)rowB * 2048 + c_pr];
        const float* w0 = Wb + (size_t)b_k * F5H + col0;
        const float* w4 = w0 + (size_t)4 * F5H;
#pragma unroll
        for (int m = 0; m < 8; m++) {
            int n = c_ri + 16 * m;
            float h0, l0, h4, l4;
            split2(w0[n], h0, l0);
            split2(w4[n], h4, l4);
            Bf[c_pr * 130 + n] = make_float4(h0, h4, l0, l4);
        }
    }
    __syncthreads();

    // ---- main loop: 16 stages of 32 K ----
    for (int kt = 0; kt < 16; kt++) {
        int cur = kt & 1;
        float4 pa1, pa2;
        float wk[8], wk4[8];
        if (kt < 15) {
            int pib = (kt + 1) * 16 + c_pr;
            pa1 = Apk[(size_t)rowA * 2048 + pib];
            pa2 = Apk[(size_t)rowB * 2048 + pib];
            const float* w0 = Wb + (size_t)((kt + 1) * 32 + b_k) * F5H + col0;
            const float* w4 = w0 + (size_t)4 * F5H;
#pragma unroll
            for (int m = 0; m < 8; m++) {
                int n = c_ri + 16 * m;
                wk[m] = w0[n];
                wk4[m] = w4[n];
            }
        }
        const float4* Ac = Af + cur * 544;
        const float4* Bc = Bf + cur * 2080;
#pragma unroll
        for (int k8 = 0; k8 < 4; k8++) {
            int pr = k8 * 4 + tig;
            float4 f1 = Ac[pr * 34 + wm * 16 + tg];
            float4 f2 = Ac[pr * 34 + wm * 16 + tg + 8];
            uint32_t ah0 = __float_as_uint(f1.x), ah1 = __float_as_uint(f2.x);
            uint32_t ah2 = __float_as_uint(f1.y), ah3 = __float_as_uint(f2.y);
            uint32_t al0 = __float_as_uint(f1.z), al1 = __float_as_uint(f2.z);
            uint32_t al2 = __float_as_uint(f1.w), al3 = __float_as_uint(f2.w);
#pragma unroll
            for (int nn = 0; nn < 4; nn++) {
                float4 bb = Bc[pr * 130 + wn * 32 + nn * 8 + tg];
                uint32_t bh0 = __float_as_uint(bb.x), bh1 = __float_as_uint(bb.y);
                uint32_t bl0 = __float_as_uint(bb.z), bl1 = __float_as_uint(bb.w);
                mma8(acc[nn][0], acc[nn][1], acc[nn][2], acc[nn][3],
                     ah0, ah1, ah2, ah3, bh0, bh1);
                mma8(acc[nn][0], acc[nn][1], acc[nn][2], acc[nn][3],
                     ah0, ah1, ah2, ah3, bl0, bl1);
                mma8(acc[nn][0], acc[nn][1], acc[nn][2], acc[nn][3],
                     al0, al1, al2, al3, bh0, bh1);
            }
        }
        if (kt < 15) {
            int nb = cur ^ 1;
            Af[nb * 544 + c_pr * 34 + c_ri]      = pa1;
            Af[nb * 544 + c_pr * 34 + c_ri + 16] = pa2;
#pragma unroll
            for (int m = 0; m < 8; m++) {
                int n = c_ri + 16 * m;
                float h0, l0, h4, l4;
                split2(wk[m], h0, l0);
                split2(wk4[m], h4, l4);
                Bf[nb * 2080 + c_pr * 130 + n] = make_float4(h0, h4, l0, l4);
            }
            __syncthreads();
        }
    }

    float* outp = g_partial + (size_t)ks * 128 * F5H;
    int rlo = s_list[wm * 16 + tg];
    int rhi = s_list[wm * 16 + tg + 8];
#pragma unroll
    for (int nn = 0; nn < 4; nn++) {
        int c = col0 + wn * 32 + nn * 8 + tig * 2;
        if (rlo >= 0)
            *(float2*)&outp[(size_t)(j * 64 + rlo) * F5H + c] = make_float2(acc[nn][0], acc[nn][1]);
        if (rhi >= 0)
            *(float2*)&outp[(size_t)(j * 64 + rhi) * F5H + c] = make_float2(acc[nn][2], acc[nn][3]);
    }
}

// ---------------- output assembly -------------------------------------------
__global__ void k_output(float* __restrict__ out) {
    size_t i = (size_t)blockIdx.x * 256 + threadIdx.x;
    size_t total = (size_t)B * T * 1536;
    if (i >= total) return;
    int c = (int)(i % 1536);
    size_t bt = i / 1536;
    int b = (int)(bt >> 7), t = (int)(bt & 127);
    float v;
    if (c < 1024) {
        size_t idx = ((size_t)t * B + b) * 1024 + c;
        v = 0.5f * (g_bufB[idx] + g_bufA[idx]);
    } else {
        int p = c - 1024;
        size_t idx = ((size_t)t * B + b) * H + p;
        v = 0.5f * (g_shareB[idx] + g_shareA[idx]);
    }
    out[i] = v;
}

// ---------------- launch ------------------------------------------------------
extern "C" void kernel_launch(void* const* d_in, const int* in_sizes, int n_in,
                              void* d_out, int out_size) {
    const float* feat = (const float*)d_in[0];
    const float* ctx  = (const float*)d_in[1];
    const float* l2sW = (const float*)d_in[2];
    const float* l2sb = (const float*)d_in[3];
    const float* sepW = (const float*)d_in[4];
    const float* sepb = (const float*)d_in[5];
    const float* aW   = (const float*)d_in[6];
    const float* ab   = (const float*)d_in[7];
    const float* Wx   = (const float*)d_in[8];
    const float* bx   = (const float*)d_in[9];
    const float* Wh   = (const float*)d_in[10];
    const float* bh   = (const float*)d_in[11];
    const float* Wc   = (const float*)d_in[12];
    const float* bc   = (const float*)d_in[13];
    float* out = (float*)d_out;

    cudaFuncSetAttribute(k_share, cudaFuncAttributeMaxDynamicSharedMemorySize, SMEM_S);
    cudaFuncSetAttribute(k_gemm, cudaFuncAttributeMaxDynamicSharedMemorySize, SMEM_G);

    k_share<<<dim3(4, 128), 256, SMEM_S>>>(feat, l2sW, l2sb);
    k_groupsep<<<B * T, 128>>>(feat, sepW, sepb);
    for (int l = 0; l < LNUM; l++) {
        for (int t = 0; t < T; t++) {
            k_step<<<B, 512>>>(ctx, aW, ab, bx, bh, bc, l, t);
            k_gemm<<<dim3(20, 2, 16), 256, SMEM_G>>>(Wx, Wh, Wc, l);
        }
        k_step<<<B, 512>>>(ctx, aW, ab, bx, bh, bc, l, T);
    }
    k_output<<<(int)(((size_t)B * T * 1536 + 255) / 256), 256>>>(out);
}